// round 11
// baseline (speedup 1.0000x reference)
#include <cuda_runtime.h>

// CategoryAwareGate: B=8, C=16, H=W=256, HID=32, N = B*H*W = 524288.
// d_out packing (float32): fused_logits[8,16,256,256] (8388608),
// expert_preferences[16,2] (32), dynamic_weights[N,16,2] (16777216).
//
// R11 = R9 + weights in __constant__ (separate const port; frees the L1/LSU
// path of 512 LDS.128/thread). Prep kernel packs -> staging global ->
// cudaMemcpyToSymbolAsync (D2D, graph-capturable) -> main kernel reads LDC/LDCU.
// block=128, 2 slots/thread, 7 CTAs/SM, logit prefetch pipeline.

static constexpr long FUSED_ELEMS = 8L * 16 * 65536;  // 8388608
static constexpr int STR = 18;                         // floats per w-row
static constexpr int SMEM_BYTES = 256 * STR * 4;       // 18432 (wbuf only)

__constant__ unsigned long long cw[1024];  // per-(p,h): [w10][w11][b1][w2diff] pairs
__constant__ unsigned long long cd2[8];    // b2diff pairs per p

__device__ unsigned long long stage_w[1024];
__device__ unsigned long long stage_b[8];

__device__ __forceinline__ unsigned long long pk2(float a, float b) {
    unsigned long long r;
    asm("mov.b64 %0, {%1, %2};" : "=l"(r) : "f"(a), "f"(b));
    return r;
}
__device__ __forceinline__ void upk2(unsigned long long v, float& a, float& b) {
    asm("mov.b64 {%0, %1}, %2;" : "=f"(a), "=f"(b) : "l"(v));
}
__device__ __forceinline__ unsigned long long fma2(unsigned long long a,
                                                   unsigned long long b,
                                                   unsigned long long c) {
    unsigned long long r;
    asm("fma.rn.f32x2 %0, %1, %2, %3;" : "=l"(r) : "l"(a), "l"(b), "l"(c));
    return r;
}
// packed relu: two scalar max.f32 on the halves (no f32x2 min/max in PTX)
__device__ __forceinline__ unsigned long long relu2(unsigned long long v) {
    unsigned long long r;
    asm("{\n\t"
        ".reg .f32 lo, hi;\n\t"
        "mov.b64 {lo, hi}, %1;\n\t"
        "max.f32 lo, lo, 0f00000000;\n\t"
        "max.f32 hi, hi, 0f00000000;\n\t"
        "mov.b64 %0, {lo, hi};\n\t"
        "}" : "=l"(r) : "l"(v));
    return r;
}

__global__ void pack_weights(const float* __restrict__ W1,
                             const float* __restrict__ b1,
                             const float* __restrict__ W2,
                             const float* __restrict__ b2) {
    const int idx = threadIdx.x;  // 256 threads: one (p,h) each
    const int p = idx >> 5, h = idx & 31;
    const int c0 = p * 2, c1 = c0 + 1;
    // W1:(C,32,2) c*64+h*2+i ; b1:(C,32) ; W2:(C,2,32) c*64+o*32+h
    stage_w[idx * 4 + 0] = pk2(W1[c0 * 64 + h * 2 + 0], W1[c1 * 64 + h * 2 + 0]);
    stage_w[idx * 4 + 1] = pk2(W1[c0 * 64 + h * 2 + 1], W1[c1 * 64 + h * 2 + 1]);
    stage_w[idx * 4 + 2] = pk2(b1[c0 * 32 + h], b1[c1 * 32 + h]);
    stage_w[idx * 4 + 3] = pk2(W2[c0 * 64 + h] - W2[c0 * 64 + 32 + h],
                               W2[c1 * 64 + h] - W2[c1 * 64 + 32 + h]);
    if (idx < 8)
        stage_b[idx] = pk2(b2[2 * idx * 2] - b2[2 * idx * 2 + 1],
                           b2[(2 * idx + 1) * 2] - b2[(2 * idx + 1) * 2 + 1]);
}

__global__ void __launch_bounds__(128, 7)
gate_fuse_kernel(const float* __restrict__ swin, const float* __restrict__ gru,
                 float* __restrict__ fused, float* __restrict__ dw) {
    extern __shared__ __align__(16) unsigned char smem_raw[];
    float* wbuf = reinterpret_cast<float*>(smem_raw);  // 256 rows x 18

    const int tid = threadIdx.x;
    const int warp = tid >> 5;
    const int lane = tid & 31;

    // Block = 256 consecutive pixels (256 blocks/image: never straddles).
    const int n0 = blockIdx.x * 256 + tid;  // slot s pixel: n0 + s*128
    const long base = (long)(n0 >> 16) * (16L * 65536) + (n0 & 65535);

    // Phase A: softmax denominators (exps recomputed per pair later).
    float rs[2], rg[2];
#pragma unroll
    for (int s = 0; s < 2; s++) {
        const long bs = base + s * 128;
        float ss = 0.f, sg = 0.f;
#pragma unroll
        for (int c = 0; c < 16; c++) {
            ss += __expf(__ldg(swin + bs + (long)c * 65536));
            sg += __expf(__ldg(gru + bs + (long)c * 65536));
        }
        rs[s] = __fdividef(1.f, ss);
        rg[s] = __fdividef(1.f, sg);
    }

    float* myrow = wbuf + tid * STR;  // rows: [slot*128 + tid]

    // Prologue: load pair-0 logits. (c0 half in .x, c1 half in .y)
    float2 csl[2], cgl[2];
#pragma unroll
    for (int s = 0; s < 2; s++) {
        const long o = base + s * 128;
        csl[s] = make_float2(__ldg(swin + o), __ldg(swin + o + 65536));
        cgl[s] = make_float2(__ldg(gru + o), __ldg(gru + o + 65536));
    }

#pragma unroll 1
    for (int p = 0; p < 8; p++) {
        // Prefetch pair p+1 logits (wrap keeps it in-bounds; discarded at p=7).
        const int pn = (p + 1) & 7;
        const long pno = base + (long)(2 * pn) * 65536;
        float2 nsl[2], ngl[2];
#pragma unroll
        for (int s = 0; s < 2; s++) {
            const long o = pno + s * 128;
            nsl[s] = make_float2(__ldg(swin + o), __ldg(swin + o + 65536));
            ngl[s] = make_float2(__ldg(gru + o), __ldg(gru + o + 65536));
        }

        const unsigned long long d2i = cd2[p];
        unsigned long long xp[2], yp[2], d2[2];
#pragma unroll
        for (int s = 0; s < 2; s++) {
            xp[s] = pk2(__expf(csl[s].x) * rs[s], __expf(csl[s].y) * rs[s]);
            yp[s] = pk2(__expf(cgl[s].x) * rg[s], __expf(cgl[s].y) * rg[s]);
            d2[s] = d2i;
        }

        const unsigned long long* wp = cw + p * 128;  // constant bank
#pragma unroll
        for (int h = 0; h < 32; h++) {
            const unsigned long long wa0 = wp[h * 4 + 0];
            const unsigned long long wa1 = wp[h * 4 + 1];
            const unsigned long long wb0 = wp[h * 4 + 2];
            const unsigned long long wb1 = wp[h * 4 + 3];
#pragma unroll
            for (int s = 0; s < 2; s++) {
                unsigned long long t = fma2(wa0, xp[s], wb0);
                t = fma2(wa1, yp[s], t);
                d2[s] = fma2(wb1, relu2(t), d2[s]);
            }
        }

        const long po = base + (long)(2 * p) * 65536;
#pragma unroll
        for (int s = 0; s < 2; s++) {
            float d0, d1;
            upk2(d2[s], d0, d1);
            const float w0 = __fdividef(1.f, 1.f + __expf(-d0));
            const float w1 = __fdividef(1.f, 1.f + __expf(-d1));
            *reinterpret_cast<float2*>(myrow + s * 128 * STR + 2 * p) =
                make_float2(w0, w1);
            const long o = po + s * 128;
            fused[o] = fmaf(w0, csl[s].x - cgl[s].x, cgl[s].x);
            fused[o + 65536] = fmaf(w1, csl[s].y - cgl[s].y, cgl[s].y);
            csl[s] = nsl[s];
            cgl[s] = ngl[s];
        }
    }

    __syncwarp();  // drain reads only this warp's own rows
    // Drain: per (slot, warp): 32 px * 32 floats = 4KB contiguous in dw.
#pragma unroll
    for (int s = 0; s < 2; s++) {
        const float* rows = wbuf + (s * 128 + warp * 32) * STR;
        const long g = ((long)blockIdx.x * 256 + s * 128 + warp * 32) * 32;
#pragma unroll
        for (int k = 0; k < 8; k++) {
            const int px = 4 * k + (lane >> 3);
            const int pr = lane & 7;
            const float2 w =
                *reinterpret_cast<const float2*>(rows + px * STR + pr * 2);
            *reinterpret_cast<float4*>(dw + g + k * 128 + lane * 4) =
                make_float4(w.x, 1.f - w.x, w.y, 1.f - w.y);
        }
    }
}

extern "C" void kernel_launch(void* const* d_in, const int* in_sizes, int n_in,
                              void* d_out, int out_size) {
    const float* swin = (const float*)d_in[0];
    const float* gru  = (const float*)d_in[1];
    const float* W1   = (const float*)d_in[2];
    const float* b1   = (const float*)d_in[3];
    const float* W2   = (const float*)d_in[4];
    const float* b2   = (const float*)d_in[5];
    const float* pref = (const float*)d_in[6];

    float* out     = (float*)d_out;
    float* fusedp  = out;                     // 8388608
    float* prefout = out + FUSED_ELEMS;       // 32
    float* dwp     = out + FUSED_ELEMS + 32;  // 16777216

    cudaMemcpyAsync(prefout, pref, 32 * sizeof(float), cudaMemcpyDeviceToDevice);
    pack_weights<<<1, 256>>>(W1, b1, W2, b2);

    void* stage_w_ptr = nullptr;
    void* stage_b_ptr = nullptr;
    cudaGetSymbolAddress(&stage_w_ptr, stage_w);
    cudaGetSymbolAddress(&stage_b_ptr, stage_b);
    cudaMemcpyToSymbolAsync(cw, stage_w_ptr, 1024 * 8, 0,
                            cudaMemcpyDeviceToDevice);
    cudaMemcpyToSymbolAsync(cd2, stage_b_ptr, 8 * 8, 0,
                            cudaMemcpyDeviceToDevice);

    gate_fuse_kernel<<<2048, 128, SMEM_BYTES>>>(swin, gru, fusedp, dwp);
}

// round 12
// speedup vs baseline: 1.4766x; 1.4766x over previous
#include <cuda_runtime.h>

// CategoryAwareGate: B=8, C=16, H=W=256, HID=32, N = B*H*W = 524288.
// d_out packing (float32): fused_logits[8,16,256,256] (8388608),
// expert_preferences[16,2] (32), dynamic_weights[N,16,2] (16777216).
//
// R12 = R9 chassis (smem weights, 7 CTAs/SM, 28 warps) +
//  - adjacent pixel pairs (n0,n0+1) per thread: LDG.64/STG.64 vector ops
//  - dual accumulators (even/odd h) halving the serial FMA chain
//  - de-interleaved dw staging (px1 rows at +16-word pad: bank-clean)

static constexpr long FUSED_ELEMS = 8L * 16 * 65536;  // 8388608
static constexpr int STR = 18;                 // words per w-row
static constexpr int HALF_OFF = 128 * STR + 16;  // px1 rows offset (words); +16 shifts banks by 8
static constexpr int WBUF_WORDS = HALF_OFF + 128 * STR;  // 4624
static constexpr int SMEM_BYTES = 8192 + 64 + WBUF_WORDS * 4;  // 26752

__device__ __forceinline__ unsigned long long pk2(float a, float b) {
    unsigned long long r;
    asm("mov.b64 %0, {%1, %2};" : "=l"(r) : "f"(a), "f"(b));
    return r;
}
__device__ __forceinline__ void upk2(unsigned long long v, float& a, float& b) {
    asm("mov.b64 {%0, %1}, %2;" : "=f"(a), "=f"(b) : "l"(v));
}
__device__ __forceinline__ unsigned long long fma2(unsigned long long a,
                                                   unsigned long long b,
                                                   unsigned long long c) {
    unsigned long long r;
    asm("fma.rn.f32x2 %0, %1, %2, %3;" : "=l"(r) : "l"(a), "l"(b), "l"(c));
    return r;
}
__device__ __forceinline__ unsigned long long add2(unsigned long long a,
                                                   unsigned long long b) {
    unsigned long long r;
    asm("add.rn.f32x2 %0, %1, %2;" : "=l"(r) : "l"(a), "l"(b));
    return r;
}
// packed relu: two scalar max.f32 on the halves (no f32x2 min/max in PTX)
__device__ __forceinline__ unsigned long long relu2(unsigned long long v) {
    unsigned long long r;
    asm("{\n\t"
        ".reg .f32 lo, hi;\n\t"
        "mov.b64 {lo, hi}, %1;\n\t"
        "max.f32 lo, lo, 0f00000000;\n\t"
        "max.f32 hi, hi, 0f00000000;\n\t"
        "mov.b64 %0, {lo, hi};\n\t"
        "}" : "=l"(r) : "l"(v));
    return r;
}

__global__ void __launch_bounds__(128, 7)
gate_fuse_kernel(const float* __restrict__ swin, const float* __restrict__ gru,
                 const float* __restrict__ W1, const float* __restrict__ b1,
                 const float* __restrict__ W2, const float* __restrict__ b2,
                 float* __restrict__ fused, float* __restrict__ dw) {
    extern __shared__ __align__(16) unsigned char smem_raw[];
    unsigned long long* sw = reinterpret_cast<unsigned long long*>(smem_raw);  // 1024 u64
    float* sb2d = reinterpret_cast<float*>(smem_raw + 8192);                   // 16 floats
    float* wbuf = reinterpret_cast<float*>(smem_raw + 8192 + 64);

    const int tid = threadIdx.x;
    const int warp = tid >> 5;
    const int lane = tid & 31;

    // Pack per-(class-pair p, h): [w10 pair][w11 pair][b1 pair][w2diff pair]
    for (int idx = tid; idx < 256; idx += 128) {
        const int p = idx >> 5, h = idx & 31;
        const int c0 = p * 2, c1 = c0 + 1;
        // W1:(C,32,2) c*64+h*2+i ; b1:(C,32) ; W2:(C,2,32) c*64+o*32+h
        sw[idx * 4 + 0] = pk2(W1[c0 * 64 + h * 2 + 0], W1[c1 * 64 + h * 2 + 0]);
        sw[idx * 4 + 1] = pk2(W1[c0 * 64 + h * 2 + 1], W1[c1 * 64 + h * 2 + 1]);
        sw[idx * 4 + 2] = pk2(b1[c0 * 32 + h], b1[c1 * 32 + h]);
        sw[idx * 4 + 3] = pk2(W2[c0 * 64 + h] - W2[c0 * 64 + 32 + h],
                              W2[c1 * 64 + h] - W2[c1 * 64 + 32 + h]);
    }
    if (tid < 16) sb2d[tid] = b2[tid * 2] - b2[tid * 2 + 1];
    __syncthreads();

    // Thread owns adjacent pixels n0, n0+1. Block = 256 consecutive pixels.
    const int n0 = blockIdx.x * 256 + tid * 2;
    const long base = (long)(n0 >> 16) * (16L * 65536) + (n0 & 65535);

    // Phase A: softmax denominators for both pixels (vector loads).
    float ss0 = 0.f, ss1 = 0.f, sg0 = 0.f, sg1 = 0.f;
#pragma unroll
    for (int c = 0; c < 16; c++) {
        const float2 v = *reinterpret_cast<const float2*>(swin + base + (long)c * 65536);
        const float2 g = *reinterpret_cast<const float2*>(gru + base + (long)c * 65536);
        ss0 += __expf(v.x); ss1 += __expf(v.y);
        sg0 += __expf(g.x); sg1 += __expf(g.y);
    }
    const float rs0 = __fdividef(1.f, ss0), rs1 = __fdividef(1.f, ss1);
    const float rg0 = __fdividef(1.f, sg0), rg1 = __fdividef(1.f, sg1);

    float* row0 = wbuf + tid * STR;             // px0 w-row
    float* row1 = wbuf + HALF_OFF + tid * STR;  // px1 w-row

#pragma unroll 1
    for (int p = 0; p < 8; p++) {
        const long po = base + (long)(2 * p) * 65536;
        // A0=(px0.c0, px1.c0), A1=(px0.c1, px1.c1); same for gru.
        const float2 A0 = *reinterpret_cast<const float2*>(swin + po);
        const float2 A1 = *reinterpret_cast<const float2*>(swin + po + 65536);
        const float2 G0 = *reinterpret_cast<const float2*>(gru + po);
        const float2 G1 = *reinterpret_cast<const float2*>(gru + po + 65536);

        const unsigned long long xp0 = pk2(__expf(A0.x) * rs0, __expf(A1.x) * rs0);
        const unsigned long long xp1 = pk2(__expf(A0.y) * rs1, __expf(A1.y) * rs1);
        const unsigned long long yp0 = pk2(__expf(G0.x) * rg0, __expf(G1.x) * rg0);
        const unsigned long long yp1 = pk2(__expf(G0.y) * rg1, __expf(G1.y) * rg1);

        const unsigned long long d2i =
            *reinterpret_cast<const unsigned long long*>(sb2d + 2 * p);
        unsigned long long d2e0 = d2i, d2o0 = 0ULL;  // px0: even/odd h chains
        unsigned long long d2e1 = d2i, d2o1 = 0ULL;  // px1

        const unsigned long long* wp = sw + p * 128;
#pragma unroll
        for (int h = 0; h < 32; h += 2) {
            {
                const ulonglong2 wA = *reinterpret_cast<const ulonglong2*>(wp + h * 4);
                const ulonglong2 wB = *reinterpret_cast<const ulonglong2*>(wp + h * 4 + 2);
                unsigned long long t0 = fma2(wA.x, xp0, wB.x);
                t0 = fma2(wA.y, yp0, t0);
                d2e0 = fma2(wB.y, relu2(t0), d2e0);
                unsigned long long t1 = fma2(wA.x, xp1, wB.x);
                t1 = fma2(wA.y, yp1, t1);
                d2e1 = fma2(wB.y, relu2(t1), d2e1);
            }
            {
                const ulonglong2 wA = *reinterpret_cast<const ulonglong2*>(wp + h * 4 + 4);
                const ulonglong2 wB = *reinterpret_cast<const ulonglong2*>(wp + h * 4 + 6);
                unsigned long long t0 = fma2(wA.x, xp0, wB.x);
                t0 = fma2(wA.y, yp0, t0);
                d2o0 = fma2(wB.y, relu2(t0), d2o0);
                unsigned long long t1 = fma2(wA.x, xp1, wB.x);
                t1 = fma2(wA.y, yp1, t1);
                d2o1 = fma2(wB.y, relu2(t1), d2o1);
            }
        }

        float d00, d01, d10, d11;
        upk2(add2(d2e0, d2o0), d00, d01);  // px0: classes c0, c1
        upk2(add2(d2e1, d2o1), d10, d11);  // px1
        const float w00 = __fdividef(1.f, 1.f + __expf(-d00));
        const float w01 = __fdividef(1.f, 1.f + __expf(-d01));
        const float w10 = __fdividef(1.f, 1.f + __expf(-d10));
        const float w11 = __fdividef(1.f, 1.f + __expf(-d11));

        *reinterpret_cast<float2*>(row0 + 2 * p) = make_float2(w00, w01);
        *reinterpret_cast<float2*>(row1 + 2 * p) = make_float2(w10, w11);

        // fused, vectorized over the pixel pair per class plane
        *reinterpret_cast<float2*>(fused + po) =
            make_float2(fmaf(w00, A0.x - G0.x, G0.x), fmaf(w10, A0.y - G0.y, G0.y));
        *reinterpret_cast<float2*>(fused + po + 65536) =
            make_float2(fmaf(w01, A1.x - G1.x, G1.x), fmaf(w11, A1.y - G1.y, G1.y));
    }

    __syncwarp();  // drain reads only this warp's own rows
    // Drain: warp's 64 px * 32 floats = 8KB contiguous in dw.
    {
        const long g = ((long)blockIdx.x * 256 + warp * 64) * 32;
        const int j = lane & 7;  // class-pair within px row
#pragma unroll
        for (int k = 0; k < 16; k++) {
            const int px_in = 4 * k + (lane >> 3);      // 0..63 within warp
            const int s = px_in & 1;                    // px parity
            const int t = warp * 32 + (px_in >> 1);     // owning thread row
            const float2 w = *reinterpret_cast<const float2*>(
                wbuf + s * HALF_OFF + t * STR + 2 * j);
            *reinterpret_cast<float4*>(dw + g + k * 128 + lane * 4) =
                make_float4(w.x, 1.f - w.x, w.y, 1.f - w.y);
        }
    }
}

extern "C" void kernel_launch(void* const* d_in, const int* in_sizes, int n_in,
                              void* d_out, int out_size) {
    const float* swin = (const float*)d_in[0];
    const float* gru  = (const float*)d_in[1];
    const float* W1   = (const float*)d_in[2];
    const float* b1   = (const float*)d_in[3];
    const float* W2   = (const float*)d_in[4];
    const float* b2   = (const float*)d_in[5];
    const float* pref = (const float*)d_in[6];

    float* out     = (float*)d_out;
    float* fusedp  = out;                     // 8388608
    float* prefout = out + FUSED_ELEMS;       // 32
    float* dwp     = out + FUSED_ELEMS + 32;  // 16777216

    cudaFuncSetAttribute(gate_fuse_kernel,
                         cudaFuncAttributeMaxDynamicSharedMemorySize, SMEM_BYTES);
    cudaMemcpyAsync(prefout, pref, 32 * sizeof(float), cudaMemcpyDeviceToDevice);
    gate_fuse_kernel<<<2048, 128, SMEM_BYTES>>>(swin, gru, W1, b1, W2, b2, fusedp, dwp);
}